// round 1
// baseline (speedup 1.0000x reference)
#include <cuda_runtime.h>
#include <math_constants.h>

// Problem constants (fixed by the dataset)
#define B_      128
#define L_I     2
#define L_Q     10
#define N_ACT   8
#define IM      64
#define IMP     66            // 64 + halo
#define NPIX    4096          // 64*64
#define NTHR    512
#define PPT     8             // pixels per thread = 4096/512

// smem layout (bytes)
#define OFF_QR    0                       // 10*4096*4 = 163840 (also input staging alias: 2*4096*4=32768)
#define OFF_R     163840                  // 66*66*4   = 17424
#define OFF_V     181264                  // 66*66*4   = 17424
#define OFF_WEFF  198688                  // 18*4      = 72
#define OFF_QW    198760                  // 90*4      = 360
#define OFF_WW    199120                  // 90*4      = 360
#define OFF_QOUT  199480                  // 10*4      = 40
#define OFF_MISC  199520                  // flag(int) + beff(float) = 8 (pad to 16)
#define SMEM_TOT  199536

#define Q_ELEMS   (B_ * L_Q * NPIX)       // 5242880
#define LOGIT_OFF Q_ELEMS
#define ACT_OFF   (Q_ELEMS + B_ * N_ACT)  // 5243904

__global__ __launch_bounds__(NTHR, 1)
void vin_main_kernel(const float* __restrict__ in,
                     const int*   __restrict__ sx_,
                     const int*   __restrict__ sy_,
                     const int*   __restrict__ kptr,   // may be null
                     const float* __restrict__ h_w,
                     const float* __restrict__ h_b,
                     const float* __restrict__ r_w,
                     const float* __restrict__ q_w,
                     const float* __restrict__ w,
                     const float* __restrict__ fc_w,
                     float* __restrict__ out)
{
    extern __shared__ char smem[];
    float* qr    = (float*)(smem + OFF_QR);    // [10*4096] conv(r, q_w) — loop-invariant
    float* in_s  = (float*)(smem + OFF_QR);    // staging alias [2*4096], dead before qr is written
    float* r_s   = (float*)(smem + OFF_R);     // [66*66] with zero halo
    float* v_s   = (float*)(smem + OFF_V);     // [66*66] with zero halo
    float* weff  = (float*)(smem + OFF_WEFF);  // [18]  collapsed h_w∘r_w
    float* qw_s  = (float*)(smem + OFF_QW);    // [90]
    float* ww_s  = (float*)(smem + OFF_WW);    // [90]
    float* qout  = (float*)(smem + OFF_QOUT);  // [10]
    int*   flag  = (int*)  (smem + OFF_MISC);
    float* beff  = (float*)(smem + OFF_MISC + 4);

    const int b   = blockIdx.x;
    const int tid = threadIdx.x;

    // ---- stage input image into smem (2*4096 floats = 2048 float4) ----
    {
        const float4* src = (const float4*)(in + (size_t)b * L_I * NPIX);
        float4* dst = (float4*)in_s;
        for (int i = tid; i < (L_I * NPIX) / 4; i += NTHR) dst[i] = src[i];
    }

    // ---- zero halos of r_s / v_s (zero everything, interiors overwritten) ----
    for (int i = tid; i < IMP * IMP; i += NTHR) { r_s[i] = 0.f; v_s[i] = 0.f; }

    // ---- collapsed weights: weff[i*9+t] = sum_c r_w[c] * h_w[(c*2+i)*9+t] ----
    if (tid < 18) {
        const int i = tid / 9, t = tid % 9;
        float acc = 0.f;
        for (int c = 0; c < 150; c++) acc += r_w[c] * h_w[(c * L_I + i) * 9 + t];
        weff[tid] = acc;
    }
    if (tid == 18) {
        float acc = 0.f;
        for (int c = 0; c < 150; c++) acc += r_w[c] * h_b[c];
        *beff = acc;
    }
    if (tid == 19) *flag = 0;
    if (tid >= 32 && tid < 122)  qw_s[tid - 32]  = q_w[tid - 32];
    if (tid >= 128 && tid < 218) ww_s[tid - 128] = w[tid - 128];
    __syncthreads();

    // detect whether w (the v-path filter) is all-zero (benign race on flag)
    if (tid < 90 && ww_s[tid] != 0.f) *flag = 1;

    // ---- r = conv3x3(input, weff, pad=1) + beff ----
    {
        const float be = *beff;  // read before it could matter; beff written pre-sync
        #pragma unroll
        for (int c = 0; c < PPT; c++) {
            const int p = tid + c * NTHR;
            const int x = p >> 6, y = p & 63;
            float acc = be;
            #pragma unroll
            for (int i = 0; i < L_I; i++) {
                #pragma unroll
                for (int kh = 0; kh < 3; kh++) {
                    const int ix = x + kh - 1;
                    if (ix < 0 || ix > 63) continue;
                    #pragma unroll
                    for (int kw = 0; kw < 3; kw++) {
                        const int iy = y + kw - 1;
                        if (iy < 0 || iy > 63) continue;
                        acc += in_s[(i * IM + ix) * IM + iy] * weff[i * 9 + kh * 3 + kw];
                    }
                }
            }
            r_s[(x + 1) * IMP + (y + 1)] = acc;
        }
    }
    __syncthreads();   // in_s fully consumed; qr region free to write

    // ---- qr[o] = conv3x3(r, q_w[o], pad=1);  v0 = max_o qr[o] ----
    #pragma unroll
    for (int c = 0; c < PPT; c++) {
        const int p = tid + c * NTHR;
        const int x = p >> 6, y = p & 63;
        float t[9];
        #pragma unroll
        for (int kh = 0; kh < 3; kh++)
            #pragma unroll
            for (int kw = 0; kw < 3; kw++)
                t[kh * 3 + kw] = r_s[(x + kh) * IMP + (y + kw)];
        float vmax = -CUDART_INF_F;
        #pragma unroll
        for (int o = 0; o < L_Q; o++) {
            float a = 0.f;
            #pragma unroll
            for (int j = 0; j < 9; j++) a += t[j] * qw_s[o * 9 + j];
            qr[o * NPIX + p] = a;
            vmax = fmaxf(vmax, a);
        }
        v_s[(x + 1) * IMP + (y + 1)] = vmax;
    }
    __syncthreads();

    const int f = *flag;

    // ---- value-iteration loop (skipped entirely when w == 0) ----
    if (f) {
        const int kk = (kptr != nullptr) ? *kptr : 40;
        for (int it = 0; it < kk - 1; it++) {
            float nv[PPT];
            #pragma unroll
            for (int c = 0; c < PPT; c++) {
                const int p = tid + c * NTHR;
                const int x = p >> 6, y = p & 63;
                float t[9];
                #pragma unroll
                for (int kh = 0; kh < 3; kh++)
                    #pragma unroll
                    for (int kw = 0; kw < 3; kw++)
                        t[kh * 3 + kw] = v_s[(x + kh) * IMP + (y + kw)];
                float vmax = -CUDART_INF_F;
                #pragma unroll
                for (int o = 0; o < L_Q; o++) {
                    float a = qr[o * NPIX + p];
                    #pragma unroll
                    for (int j = 0; j < 9; j++) a += t[j] * ww_s[o * 9 + j];
                    vmax = fmaxf(vmax, a);
                }
                nv[c] = vmax;
            }
            __syncthreads();
            #pragma unroll
            for (int c = 0; c < PPT; c++) {
                const int p = tid + c * NTHR;
                const int x = p >> 6, y = p & 63;
                v_s[(x + 1) * IMP + (y + 1)] = nv[c];
            }
            __syncthreads();
        }
    }

    // ---- final q = qr + conv(v, w) -> global ----
    float* outb = out + (size_t)b * L_Q * NPIX;
    if (!f) {
        // q == qr exactly: vectorized smem -> gmem copy
        const float4* src = (const float4*)qr;
        float4* dst = (float4*)outb;
        #pragma unroll
        for (int c = 0; c < (L_Q * NPIX / 4) / NTHR; c++)
            dst[tid + c * NTHR] = src[tid + c * NTHR];
    } else {
        #pragma unroll
        for (int c = 0; c < PPT; c++) {
            const int p = tid + c * NTHR;
            const int x = p >> 6, y = p & 63;
            float t[9];
            #pragma unroll
            for (int kh = 0; kh < 3; kh++)
                #pragma unroll
                for (int kw = 0; kw < 3; kw++)
                    t[kh * 3 + kw] = v_s[(x + kh) * IMP + (y + kw)];
            #pragma unroll
            for (int o = 0; o < L_Q; o++) {
                float a = qr[o * NPIX + p];
                #pragma unroll
                for (int j = 0; j < 9; j++) a += t[j] * ww_s[o * 9 + j];
                outb[o * NPIX + p] = a;
            }
        }
    }

    // ---- gather q[b,:,sx,sy] from smem + logits ----
    __syncthreads();
    const int sx = sx_[b], sy = sy_[b];
    if (tid < L_Q) {
        float a = qr[tid * NPIX + sx * IM + sy];
        if (f) {
            #pragma unroll
            for (int kh = 0; kh < 3; kh++)
                #pragma unroll
                for (int kw = 0; kw < 3; kw++)
                    a += v_s[(sx + kh) * IMP + (sy + kw)] * ww_s[tid * 9 + kh * 3 + kw];
        }
        qout[tid] = a;
    }
    __syncthreads();
    if (tid < N_ACT) {
        float a = 0.f;
        #pragma unroll
        for (int o = 0; o < L_Q; o++) a += fc_w[tid * L_Q + o] * qout[o];
        out[LOGIT_OFF + b * N_ACT + tid] = a;
    }
}

// Global argmax over all B*N_ACT logits (first occurrence wins, like jnp.argmax)
__global__ void vin_argmax_kernel(const float* __restrict__ logits, float* __restrict__ action)
{
    __shared__ float sv[256];
    __shared__ int   si[256];
    const int t = threadIdx.x;
    float best = -CUDART_INF_F;
    int   bi   = 0;
    for (int i = t; i < B_ * N_ACT; i += 256) {
        const float v = logits[i];
        if (v > best) { best = v; bi = i; }   // ascending i: strict > keeps first
    }
    sv[t] = best; si[t] = bi;
    __syncthreads();
    for (int s = 128; s > 0; s >>= 1) {
        if (t < s) {
            if (sv[t + s] > sv[t] || (sv[t + s] == sv[t] && si[t + s] < si[t])) {
                sv[t] = sv[t + s]; si[t] = si[t + s];
            }
        }
        __syncthreads();
    }
    if (t == 0) action[0] = (float)si[0];
}

extern "C" void kernel_launch(void* const* d_in, const int* in_sizes, int n_in,
                              void* d_out, int out_size)
{
    // Inputs (metadata order): input_view, state_x, state_y, [k], h_w, h_b, r_w, q_w, w, fc_w
    // Locate h_w (the only size-2700 input) to learn whether scalar k is present.
    int hw_idx = -1;
    for (int i = 0; i < n_in; i++) {
        if (in_sizes[i] == 2700) { hw_idx = i; break; }
    }
    if (hw_idx < 0) hw_idx = 4;  // fallback: assume k present

    const float* in_v = (const float*)d_in[0];
    const int*   sx   = (const int*)d_in[1];
    const int*   sy   = (const int*)d_in[2];
    const int*   kptr = (hw_idx == 4) ? (const int*)d_in[3] : nullptr;
    const float* h_w  = (const float*)d_in[hw_idx];
    const float* h_b  = (const float*)d_in[hw_idx + 1];
    const float* r_w  = (const float*)d_in[hw_idx + 2];
    const float* q_w  = (const float*)d_in[hw_idx + 3];
    const float* w    = (const float*)d_in[hw_idx + 4];
    const float* fc_w = (const float*)d_in[hw_idx + 5];
    float* out = (float*)d_out;

    cudaFuncSetAttribute(vin_main_kernel,
                         cudaFuncAttributeMaxDynamicSharedMemorySize, SMEM_TOT);

    vin_main_kernel<<<B_, NTHR, SMEM_TOT>>>(in_v, sx, sy, kptr, h_w, h_b, r_w,
                                            q_w, w, fc_w, out);
    vin_argmax_kernel<<<1, 256>>>(out + LOGIT_OFF, out + ACT_OFF);
}

// round 2
// speedup vs baseline: 1.3907x; 1.3907x over previous
#include <cuda_runtime.h>
#include <math_constants.h>

// Problem constants (fixed by the dataset)
#define B_      128
#define L_I     2
#define L_Q     10
#define N_ACT   8
#define IM      64
#define IMP     66            // 64 + halo
#define NPIX    4096          // 64*64
#define NTHR    512
#define PPT     8             // pixels per thread = 4096/512

// smem layout (bytes)
#define OFF_QR    0                       // 10*4096*4 = 163840 (aliased: input staging 32768 + weight staging 13040)
#define OFF_R     163840                  // 66*66*4   = 17424
#define OFF_V     181264                  // 66*66*4   = 17424
#define OFF_WEFF  198688                  // 18*4
#define OFF_QW    198760                  // 90*4
#define OFF_WW    199120                  // 90*4
#define OFF_FC    199480                  // 80*4
#define OFF_QOUT  199800                  // 10*4
#define OFF_MISC  199840                  // flag(4) + beff(4) + larr[8](32)
#define SMEM_TOT  199888

// staging offsets (floats, inside the qr alias region, after the 8192-float input)
#define STG_BASE  8192
#define STG_HW    (STG_BASE + 0)          // 2700
#define STG_HB    (STG_BASE + 2700)       // 150
#define STG_RW    (STG_BASE + 2850)       // 150
#define STG_QW    (STG_BASE + 3000)       // 90
#define STG_WW    (STG_BASE + 3090)       // 90
#define STG_FC    (STG_BASE + 3180)       // 80

#define Q_ELEMS   (B_ * L_Q * NPIX)       // 5242880
#define LOGIT_OFF Q_ELEMS
#define ACT_OFF   (Q_ELEMS + B_ * N_ACT)  // 5243904

// grid-wide argmax state (self-resetting each launch -> graph-replay safe)
__device__ unsigned long long g_best  = 0ULL;
__device__ unsigned int       g_count = 0u;

__device__ __forceinline__ unsigned int ordered_f32(float f) {
    unsigned int u = __float_as_uint(f);
    return (u & 0x80000000u) ? ~u : (u | 0x80000000u);
}

__global__ __launch_bounds__(NTHR, 1)
void vin_main_kernel(const float* __restrict__ in,
                     const int*   __restrict__ sx_,
                     const int*   __restrict__ sy_,
                     const int*   __restrict__ kptr,   // may be null
                     const float* __restrict__ h_w,
                     const float* __restrict__ h_b,
                     const float* __restrict__ r_w,
                     const float* __restrict__ q_w,
                     const float* __restrict__ w,
                     const float* __restrict__ fc_w,
                     float* __restrict__ out)
{
    extern __shared__ char smem[];
    float* qr    = (float*)(smem + OFF_QR);    // [10*4096] only used in slow path
    float* in_s  = (float*)(smem + OFF_QR);    // alias [2*4096]
    float* wt_s  = (float*)(smem + OFF_QR);    // alias, indices STG_*
    float* r_s   = (float*)(smem + OFF_R);     // [66*66] zero halo
    float* v_s   = (float*)(smem + OFF_V);     // [66*66] zero halo (slow path)
    float* weff  = (float*)(smem + OFF_WEFF);  // [18]
    float* qw_s  = (float*)(smem + OFF_QW);    // [90]
    float* ww_s  = (float*)(smem + OFF_WW);    // [90]
    float* fc_s  = (float*)(smem + OFF_FC);    // [80]
    float* qout  = (float*)(smem + OFF_QOUT);  // [10]
    int*   flag  = (int*)  (smem + OFF_MISC);
    float* beff  = (float*)(smem + OFF_MISC + 4);
    float* larr  = (float*)(smem + OFF_MISC + 8);

    const int b   = blockIdx.x;
    const int tid = threadIdx.x;

    // ================= S0: stage everything (coalesced), zero r_s/v_s =================
    {
        const float4* src = (const float4*)(in + (size_t)b * L_I * NPIX);
        float4* dst = (float4*)in_s;
        #pragma unroll
        for (int i = 0; i < (L_I * NPIX / 4) / NTHR; i++)
            dst[tid + i * NTHR] = src[tid + i * NTHR];
    }
    for (int i = tid; i < 2700; i += NTHR) wt_s[STG_HW + i] = h_w[i];
    if (tid < 150) wt_s[STG_HB + tid] = h_b[tid];
    if (tid < 150) wt_s[STG_RW + tid] = r_w[tid];
    if (tid < 90)  wt_s[STG_QW + tid] = q_w[tid];
    if (tid < 90)  wt_s[STG_WW + tid] = w[tid];
    if (tid < 80)  wt_s[STG_FC + tid] = fc_w[tid];
    for (int i = tid; i < IMP * IMP; i += NTHR) { r_s[i] = 0.f; v_s[i] = 0.f; }
    if (tid == NTHR - 1) *flag = 0;
    __syncthreads();

    // ================= S1: parallel weight collapse + small copies + flag ============
    // 19 items (18 weff taps + beff), one 16-lane half-warp each. All threads
    // execute the shuffles (full mask) with invalid items contributing garbage
    // that is never written back.
    {
        const int item = tid >> 4;       // 0..31
        const int l    = tid & 15;
        float acc = 0.f;
        if (item < 18) {
            const int i = item / 9, t = item % 9;
            #pragma unroll
            for (int s = 0; s < 10; s++) {
                const int c = l + 16 * s;
                if (c < 150)
                    acc += wt_s[STG_RW + c] * wt_s[STG_HW + (c * L_I + i) * 9 + t];
            }
        } else if (item == 18) {
            #pragma unroll
            for (int s = 0; s < 10; s++) {
                const int c = l + 16 * s;
                if (c < 150) acc += wt_s[STG_RW + c] * wt_s[STG_HB + c];
            }
        }
        acc += __shfl_xor_sync(0xFFFFFFFFu, acc, 8);
        acc += __shfl_xor_sync(0xFFFFFFFFu, acc, 4);
        acc += __shfl_xor_sync(0xFFFFFFFFu, acc, 2);
        acc += __shfl_xor_sync(0xFFFFFFFFu, acc, 1);
        if (l == 0) {
            if (item < 18)       weff[item] = acc;
            else if (item == 18) *beff = acc;
        }
    }
    if (tid < 90) qw_s[tid] = wt_s[STG_QW + tid];
    if (tid < 90) ww_s[tid] = wt_s[STG_WW + tid];
    if (tid < 80) fc_s[tid] = wt_s[STG_FC + tid];
    if (tid < 90 && wt_s[STG_WW + tid] != 0.f) *flag = 1;   // benign race
    __syncthreads();

    // ================= S2: r = conv3x3(input, weff, pad=1) + beff ====================
    {
        const float be = *beff;
        #pragma unroll
        for (int c = 0; c < PPT; c++) {
            const int p = tid + c * NTHR;
            const int x = p >> 6, y = p & 63;
            float acc = be;
            #pragma unroll
            for (int i = 0; i < L_I; i++) {
                #pragma unroll
                for (int kh = 0; kh < 3; kh++) {
                    const int ix = x + kh - 1;
                    if (ix < 0 || ix > 63) continue;
                    #pragma unroll
                    for (int kw = 0; kw < 3; kw++) {
                        const int iy = y + kw - 1;
                        if (iy < 0 || iy > 63) continue;
                        acc += in_s[(i * IM + ix) * IM + iy] * weff[i * 9 + kh * 3 + kw];
                    }
                }
            }
            r_s[(x + 1) * IMP + (y + 1)] = acc;
        }
    }
    __syncthreads();   // in_s fully consumed; qr region free

    const int f = *flag;                 // stable since S1's sync
    float* outb = out + (size_t)b * L_Q * NPIX;

    if (!f) {
        // ============== FAST PATH: w == 0 -> q == conv(r, q_w), no iteration =========
        // gather for the FC head: recompute q at (sx,sy) from r_s (10 x 9 FMA)
        {
            const int sx = sx_[b], sy = sy_[b];
            if (tid < L_Q) {
                float a = 0.f;
                #pragma unroll
                for (int kh = 0; kh < 3; kh++)
                    #pragma unroll
                    for (int kw = 0; kw < 3; kw++)
                        a += r_s[(sx + kh) * IMP + (sy + kw)] * qw_s[tid * 9 + kh * 3 + kw];
                qout[tid] = a;
            }
        }
        // conv(r, q_w) straight to gmem, weights register-chunked (5 outputs/chunk)
        #pragma unroll
        for (int chunk = 0; chunk < 2; chunk++) {
            float qwr[45];
            #pragma unroll
            for (int j = 0; j < 45; j++) qwr[j] = qw_s[chunk * 45 + j];
            #pragma unroll
            for (int c = 0; c < PPT; c++) {
                const int p = tid + c * NTHR;
                const int x = p >> 6, y = p & 63;
                float t[9];
                #pragma unroll
                for (int kh = 0; kh < 3; kh++)
                    #pragma unroll
                    for (int kw = 0; kw < 3; kw++)
                        t[kh * 3 + kw] = r_s[(x + kh) * IMP + (y + kw)];
                #pragma unroll
                for (int oo = 0; oo < 5; oo++) {
                    float a = 0.f;
                    #pragma unroll
                    for (int j = 0; j < 9; j++) a += t[j] * qwr[oo * 9 + j];
                    outb[(chunk * 5 + oo) * NPIX + p] = a;
                }
            }
        }
        __syncthreads();   // qout ready for all
    } else {
        // ============== SLOW PATH: generic k-iteration loop (w != 0) =================
        // qr[o] = conv(r, q_w[o]); v0 = max_o qr[o]
        #pragma unroll
        for (int c = 0; c < PPT; c++) {
            const int p = tid + c * NTHR;
            const int x = p >> 6, y = p & 63;
            float t[9];
            #pragma unroll
            for (int kh = 0; kh < 3; kh++)
                #pragma unroll
                for (int kw = 0; kw < 3; kw++)
                    t[kh * 3 + kw] = r_s[(x + kh) * IMP + (y + kw)];
            float vmax = -CUDART_INF_F;
            #pragma unroll
            for (int o = 0; o < L_Q; o++) {
                float a = 0.f;
                #pragma unroll
                for (int j = 0; j < 9; j++) a += t[j] * qw_s[o * 9 + j];
                qr[o * NPIX + p] = a;
                vmax = fmaxf(vmax, a);
            }
            v_s[(x + 1) * IMP + (y + 1)] = vmax;
        }
        __syncthreads();

        const int kk = (kptr != nullptr) ? *kptr : 40;
        for (int it = 0; it < kk - 1; it++) {
            float nv[PPT];
            #pragma unroll
            for (int c = 0; c < PPT; c++) {
                const int p = tid + c * NTHR;
                const int x = p >> 6, y = p & 63;
                float t[9];
                #pragma unroll
                for (int kh = 0; kh < 3; kh++)
                    #pragma unroll
                    for (int kw = 0; kw < 3; kw++)
                        t[kh * 3 + kw] = v_s[(x + kh) * IMP + (y + kw)];
                float vmax = -CUDART_INF_F;
                #pragma unroll
                for (int o = 0; o < L_Q; o++) {
                    float a = qr[o * NPIX + p];
                    #pragma unroll
                    for (int j = 0; j < 9; j++) a += t[j] * ww_s[o * 9 + j];
                    vmax = fmaxf(vmax, a);
                }
                nv[c] = vmax;
            }
            __syncthreads();
            #pragma unroll
            for (int c = 0; c < PPT; c++) {
                const int p = tid + c * NTHR;
                const int x = p >> 6, y = p & 63;
                v_s[(x + 1) * IMP + (y + 1)] = nv[c];
            }
            __syncthreads();
        }

        // final q = qr + conv(v, w) -> gmem
        #pragma unroll
        for (int c = 0; c < PPT; c++) {
            const int p = tid + c * NTHR;
            const int x = p >> 6, y = p & 63;
            float t[9];
            #pragma unroll
            for (int kh = 0; kh < 3; kh++)
                #pragma unroll
                for (int kw = 0; kw < 3; kw++)
                    t[kh * 3 + kw] = v_s[(x + kh) * IMP + (y + kw)];
            #pragma unroll
            for (int o = 0; o < L_Q; o++) {
                float a = qr[o * NPIX + p];
                #pragma unroll
                for (int j = 0; j < 9; j++) a += t[j] * ww_s[o * 9 + j];
                outb[o * NPIX + p] = a;
            }
        }
        // gather q[b,:,sx,sy]
        const int sx = sx_[b], sy = sy_[b];
        if (tid < L_Q) {
            float a = qr[tid * NPIX + sx * IM + sy];
            #pragma unroll
            for (int kh = 0; kh < 3; kh++)
                #pragma unroll
                for (int kw = 0; kw < 3; kw++)
                    a += v_s[(sx + kh) * IMP + (sy + kw)] * ww_s[tid * 9 + kh * 3 + kw];
            qout[tid] = a;
        }
        __syncthreads();
    }

    // ================= epilogue: logits + fused grid-wide argmax =====================
    if (tid < N_ACT) {
        float a = 0.f;
        #pragma unroll
        for (int o = 0; o < L_Q; o++) a += fc_s[tid * L_Q + o] * qout[o];
        out[LOGIT_OFF + b * N_ACT + tid] = a;
        larr[tid] = a;
    }
    __syncthreads();
    if (tid == 0) {
        // CTA-local best (max value, smallest flat index on ties)
        float best = larr[0];
        int   bi   = b * N_ACT;
        #pragma unroll
        for (int a = 1; a < N_ACT; a++) {
            if (larr[a] > best) { best = larr[a]; bi = b * N_ACT + a; }
        }
        const unsigned long long key =
            ((unsigned long long)ordered_f32(best) << 32) |
            (unsigned long long)(0xFFFFFFFFu - (unsigned int)bi);
        atomicMax(&g_best, key);
        __threadfence();
        const unsigned int cnt = atomicAdd(&g_count, 1u);
        if (cnt == B_ - 1u) {
            const unsigned long long k2 = atomicMax(&g_best, 0ULL); // atomic read
            const unsigned int flat = 0xFFFFFFFFu - (unsigned int)(k2 & 0xFFFFFFFFu);
            out[ACT_OFF] = (float)flat;
            // reset for next (graph-replayed) launch
            g_best = 0ULL;
            __threadfence();
            atomicExch(&g_count, 0u);
        }
    }
}

extern "C" void kernel_launch(void* const* d_in, const int* in_sizes, int n_in,
                              void* d_out, int out_size)
{
    // Inputs: input_view, state_x, state_y, [k], h_w, h_b, r_w, q_w, w, fc_w
    // h_w is the only size-2700 input; its position tells us whether k is present.
    int hw_idx = -1;
    for (int i = 0; i < n_in; i++) {
        if (in_sizes[i] == 2700) { hw_idx = i; break; }
    }
    if (hw_idx < 0) hw_idx = 4;

    const float* in_v = (const float*)d_in[0];
    const int*   sx   = (const int*)d_in[1];
    const int*   sy   = (const int*)d_in[2];
    const int*   kptr = (hw_idx == 4) ? (const int*)d_in[3] : nullptr;
    const float* h_w  = (const float*)d_in[hw_idx];
    const float* h_b  = (const float*)d_in[hw_idx + 1];
    const float* r_w  = (const float*)d_in[hw_idx + 2];
    const float* q_w  = (const float*)d_in[hw_idx + 3];
    const float* w    = (const float*)d_in[hw_idx + 4];
    const float* fc_w = (const float*)d_in[hw_idx + 5];
    float* out = (float*)d_out;

    cudaFuncSetAttribute(vin_main_kernel,
                         cudaFuncAttributeMaxDynamicSharedMemorySize, SMEM_TOT);

    vin_main_kernel<<<B_, NTHR, SMEM_TOT>>>(in_v, sx, sy, kptr, h_w, h_b, r_w,
                                            q_w, w, fc_w, out);
}